// round 14
// baseline (speedup 1.0000x reference)
#include <cuda_runtime.h>
#include <cuda_bf16.h>
#include <math.h>
#include <stdint.h>

#define Bsz   32
#define Ssz   1024
#define Dsz   1280
#define CRS   768
#define HEADS 20
#define HD    64
#define NTOK  16
#define ETOK  48
#define MS    (Bsz*Ssz)
#define SCALE 0.125f

typedef __nv_bfloat16 bf16;

// ---------------- scratch (device globals: allocation-free) ----------------
__device__ bf16  g_qb [MS*Dsz];
__device__ bf16  g_z  [MS*Dsz];
__device__ bf16  g_hidb[MS*Dsz];
__device__ bf16  g_anat[Bsz*NTOK*CRS];
__device__ bf16  g_dis [Bsz*NTOK*CRS];
__device__ float g_ka [Bsz*NTOK*Dsz];
__device__ float g_va [Bsz*NTOK*Dsz];
__device__ float g_kd [Bsz*NTOK*Dsz];
__device__ float g_vd [Bsz*NTOK*Dsz];
__device__ float g_gate[Bsz*2];
__device__ bf16  g_wq  [Dsz*Dsz];
__device__ bf16  g_wout[Dsz*Dsz];
__device__ bf16  g_wka [Dsz*CRS];
__device__ bf16  g_wva [Dsz*CRS];
__device__ bf16  g_wkd [Dsz*CRS];
__device__ bf16  g_wvd [Dsz*CRS];

// ---------------- helpers ---------------------------------------------------
__device__ __forceinline__ uint32_t smem_u32(const void* p) {
    uint32_t a;
    asm("{ .reg .u64 t; cvta.to.shared.u64 t, %1; cvt.u32.u64 %0, t; }" : "=r"(a) : "l"(p));
    return a;
}
__device__ __forceinline__ void cp16(uint32_t dst, const void* src) {
    asm volatile("cp.async.cg.shared.global [%0], [%1], 16;" :: "r"(dst), "l"(src));
}
#define CP_COMMIT() asm volatile("cp.async.commit_group;" ::: "memory")

__device__ __forceinline__ uint32_t pack_bf2(float lo, float hi) {
    __nv_bfloat162 v = __floats2bfloat162_rn(lo, hi);
    return *(uint32_t*)&v;
}
__device__ __forceinline__ void ldsm4(uint32_t* r, uint32_t addr) {
    asm volatile("ldmatrix.sync.aligned.m8n8.x4.shared.b16 {%0,%1,%2,%3}, [%4];"
                 : "=r"(r[0]), "=r"(r[1]), "=r"(r[2]), "=r"(r[3]) : "r"(addr));
}
__device__ __forceinline__ void mma16(float* d, const uint32_t* a, const uint32_t* b) {
    asm volatile(
        "mma.sync.aligned.m16n8k16.row.col.f32.bf16.bf16.f32 "
        "{%0,%1,%2,%3}, {%4,%5,%6,%7}, {%8,%9}, {%0,%1,%2,%3};"
        : "+f"(d[0]), "+f"(d[1]), "+f"(d[2]), "+f"(d[3])
        : "r"(a[0]), "r"(a[1]), "r"(a[2]), "r"(a[3]), "r"(b[0]), "r"(b[1]));
}

// ---------------- bf16 mma.sync GEMM: BM=256, BN=128, BK=64, 3-stage --------
// 16 warps (4m x 4n), warp tile 64x32, 512 threads, 1 CTA/SM.
#define LDE 72
#define A_BYTES (256*LDE*2)              // 36864
#define B_BYTES (128*LDE*2)              // 18432
#define STAGE_BYTES (A_BYTES + B_BYTES)  // 55296
#define GEMM_SMEM (3*STAGE_BYTES)        // 165888

struct ProjBatch {
    const bf16* A[5];
    const bf16* W[5];
    void*       C[5];
    int         K[5];
};

__device__ __forceinline__ void gemm_core(
    const bf16* __restrict__ A, const bf16* __restrict__ W,
    void* __restrict__ C, int N, int K, int bm, int bn, bool obf,
    const float* __restrict__ bias, const float* __restrict__ res,
    uint32_t sbase, int t, int lane, int warp_m, int warp_n)
{
    const int NIT = K / 64;

    const uint32_t aLane = ((uint32_t)(warp_m*64 + (lane & 15)) * LDE
                          + ((lane >> 4) << 3)) * 2;
    const uint32_t bLane = ((uint32_t)(warp_n*32 + ((lane >> 4) << 3) + (lane & 7)) * LDE
                          + (((lane >> 3) & 1) << 3)) * 2;

    float acc[4][4][4];
    #pragma unroll
    for (int i = 0; i < 4; i++)
        #pragma unroll
        for (int j = 0; j < 4; j++)
            #pragma unroll
            for (int r = 0; r < 4; r++) acc[i][j][r] = 0.f;

    #define LOAD_STAGE(IT, S) do {                                             \
        const bf16* Ab = A + (long)bm * K + (IT) * 64;                         \
        const bf16* Wb = W + (long)bn * K + (IT) * 64;                         \
        uint32_t dA = sbase + (S) * STAGE_BYTES;                               \
        uint32_t dB = dA + A_BYTES;                                            \
        _Pragma("unroll")                                                      \
        for (int i = 0; i < 4; i++) {                                          \
            int idx = i * 512 + t; int row = idx >> 3, g = idx & 7;            \
            cp16(dA + row * (LDE*2) + g * 16, Ab + (long)row * K + g * 8);     \
        }                                                                      \
        _Pragma("unroll")                                                      \
        for (int i = 0; i < 2; i++) {                                          \
            int idx = i * 512 + t; int row = idx >> 3, g = idx & 7;            \
            cp16(dB + row * (LDE*2) + g * 16, Wb + (long)row * K + g * 8);     \
        }                                                                      \
        CP_COMMIT();                                                           \
    } while (0)

    LOAD_STAGE(0, 0);
    if (NIT > 1) LOAD_STAGE(1, 1);

    for (int it = 0; it < NIT; it++) {
        int s = it % 3;
        if (it + 1 < NIT) asm volatile("cp.async.wait_group 1;" ::: "memory");
        else              asm volatile("cp.async.wait_group 0;" ::: "memory");
        __syncthreads();
        if (it + 2 < NIT)
            LOAD_STAGE(it + 2, (it + 2) % 3);

        const uint32_t aBase = sbase + s * STAGE_BYTES + aLane;
        const uint32_t bBase = sbase + s * STAGE_BYTES + A_BYTES + bLane;
        #pragma unroll
        for (int ks = 0; ks < 4; ks++) {
            uint32_t a[4][4], bb[2][4];
            #pragma unroll
            for (int mt = 0; mt < 4; mt++)
                ldsm4(a[mt], aBase + mt * (16*LDE*2) + ks * 32);
            #pragma unroll
            for (int j = 0; j < 2; j++)
                ldsm4(bb[j], bBase + j * (16*LDE*2) + ks * 32);
            #pragma unroll
            for (int mt = 0; mt < 4; mt++)
                #pragma unroll
                for (int nt = 0; nt < 4; nt++)
                    mma16(acc[mt][nt], a[mt], &bb[nt >> 1][(nt & 1) * 2]);
        }
    }

    #pragma unroll
    for (int mt = 0; mt < 4; mt++) {
        #pragma unroll
        for (int nt = 0; nt < 4; nt++) {
            int row = bm + warp_m * 64 + mt * 16 + (lane >> 2);
            int col = bn + warp_n * 32 + nt * 8 + 2 * (lane & 3);
            float2 v0 = make_float2(acc[mt][nt][0], acc[mt][nt][1]);
            float2 v1 = make_float2(acc[mt][nt][2], acc[mt][nt][3]);
            if (obf) {
                bf16* Cb = (bf16*)C;
                *(uint32_t*)(Cb + (long)row * N + col)       = pack_bf2(v0.x, v0.y);
                *(uint32_t*)(Cb + (long)(row + 8) * N + col) = pack_bf2(v1.x, v1.y);
            } else {
                float* Cf = (float*)C;
                if (bias) {
                    float2 bb2 = *(const float2*)(bias + col);
                    v0.x += bb2.x; v0.y += bb2.y; v1.x += bb2.x; v1.y += bb2.y;
                }
                if (res) {
                    float2 r0 = *(const float2*)(res + (long)row * N + col);
                    float2 r1 = *(const float2*)(res + (long)(row + 8) * N + col);
                    v0.x += r0.x; v0.y += r0.y; v1.x += r1.x; v1.y += r1.y;
                }
                *(float2*)(Cf + (long)row * N + col) = v0;
                *(float2*)(Cf + (long)(row + 8) * N + col) = v1;
            }
        }
    }
    #undef LOAD_STAGE
}

// merged projection kernel: grid (10, 136). y<128 -> Q tiles (bm=y*256);
// y>=128 -> KV entry 1+((y-128)>>1), bm=((y-128)&1)*256 (M=512).
__global__ __launch_bounds__(512, 1)
void proj_all(ProjBatch pb) {
    extern __shared__ bf16 sm[];
    const int t = threadIdx.x;
    const int lane = t & 31, wid = t >> 5;
    const int bn = blockIdx.x * 128;
    const uint32_t sbase = smem_u32(sm);

    int e, bm;
    if (blockIdx.y < 128) { e = 0; bm = blockIdx.y * 256; }
    else { int y = blockIdx.y - 128; e = 1 + (y >> 1); bm = (y & 1) * 256; }

    gemm_core(pb.A[e], pb.W[e], pb.C[e], Dsz, pb.K[e], bm, bn, (e == 0),
              nullptr, nullptr, sbase, t, lane, wid >> 2, wid & 3);
}

__global__ __launch_bounds__(512, 1)
void gemm_out(const bf16* __restrict__ A, const bf16* __restrict__ W,
              float* __restrict__ C, int N, int K,
              const float* __restrict__ bias, const float* __restrict__ res) {
    extern __shared__ bf16 sm[];
    const int t = threadIdx.x;
    const int lane = t & 31, wid = t >> 5;
    gemm_core(A, W, C, N, K, blockIdx.y * 256, blockIdx.x * 128, false,
              bias, res, smem_u32(sm), t, lane, wid >> 2, wid & 3);
}

// ---------------- fused prep: conversions + gather + gate (one launch) ------
#define HID_BLK  40960
#define WQ_BLK   1600
#define WK_BLK   960
#define W_BLK    (2*WQ_BLK + 4*WK_BLK)   // 7040
#define GATH_BLK 1536
#define PREP_BLKS (HID_BLK + W_BLK + GATH_BLK + 32)

struct PrepArgs {
    const float* hidden;
    const float* enc;
    const float* src[6];
    bf16*        dst[6];
    const float* w_gate;
    const float* b_gate;
    const float* a_logit;
    const float* d_logit;
};

__global__ __launch_bounds__(256)
void prep_all(PrepArgs pa) {
    int bid = blockIdx.x;
    int tid = threadIdx.x;

    if (bid < HID_BLK) {
        int i = bid * 256 + tid;
        float4 v = ((const float4*)pa.hidden)[i];
        uint2 o;
        o.x = pack_bf2(v.x, v.y);
        o.y = pack_bf2(v.z, v.w);
        ((uint2*)g_hidb)[i] = o;
        return;
    }
    bid -= HID_BLK;
    if (bid < W_BLK) {
        int seg, base;
        if (bid < WQ_BLK)               { seg = 0; base = bid; }
        else if (bid < 2*WQ_BLK)        { seg = 1; base = bid - WQ_BLK; }
        else { int y = bid - 2*WQ_BLK;    seg = 2 + y / WK_BLK; base = y % WK_BLK; }
        int i = base * 256 + tid;
        float4 v = ((const float4*)pa.src[seg])[i];
        uint2 o;
        o.x = pack_bf2(v.x, v.y);
        o.y = pack_bf2(v.z, v.w);
        ((uint2*)pa.dst[seg])[i] = o;
        return;
    }
    bid -= W_BLK;
    if (bid < GATH_BLK) {
        int i = bid * 256 + tid;
        int c = i % CRS;
        int tt = (i / CRS) % NTOK;
        int b = i / (CRS*NTOK);
        g_dis [i] = __float2bfloat16_rn(pa.enc[((long)b*ETOK + tt)        * CRS + c]);
        g_anat[i] = __float2bfloat16_rn(pa.enc[((long)b*ETOK + NTOK + tt) * CRS + c]);
        return;
    }
    bid -= GATH_BLK;
    {
        int b = bid;
        __shared__ float red[256];
        float partial = 0.f;
        for (int c = tid; c < CRS; c += 256) {
            float s = 0.f;
            #pragma unroll
            for (int t2 = 0; t2 < NTOK; t2++)
                s += pa.enc[((long)b*ETOK + t2) * CRS + c];
            partial += (s * (1.0f/NTOK)) * pa.w_gate[c];
        }
        red[tid] = partial;
        __syncthreads();
        for (int off = 128; off > 0; off >>= 1) {
            if (tid < off) red[tid] += red[tid + off];
            __syncthreads();
        }
        if (tid == 0) {
            float shift = red[0] + pa.b_gate[0];
            g_gate[b*2+0] = 1.0f / (1.0f + expf(-(pa.a_logit[0] - shift)));
            g_gate[b*2+1] = 1.0f / (1.0f + expf(-(pa.d_logit[0] + shift)));
        }
    }
}

// ---------------- mma attention: one CTA = 128 queries x 1 head -------------
#define VP 24

__device__ __forceinline__ void attend_branch(
    const bf16* sK, const bf16* sV, float gate, int lane,
    const uint32_t (&qf)[2][4][4], float (&out)[2][8][4])
{
    uint32_t bk[2][4][2];
    #pragma unroll
    for (int n = 0; n < 2; n++)
        #pragma unroll
        for (int k = 0; k < 4; k++) {
            const bf16* p = &sK[(n*8 + (lane >> 2))*72 + k*16 + 2*(lane & 3)];
            bk[n][k][0] = *(const uint32_t*)p;
            bk[n][k][1] = *(const uint32_t*)(p + 8);
        }
    uint32_t bv[8][2];
    #pragma unroll
    for (int n8 = 0; n8 < 8; n8++) {
        const bf16* p = &sV[(n8*8 + (lane >> 2))*VP + 2*(lane & 3)];
        bv[n8][0] = *(const uint32_t*)p;
        bv[n8][1] = *(const uint32_t*)(p + 8);
    }

    float sc[2][2][4];
    #pragma unroll
    for (int m = 0; m < 2; m++)
        #pragma unroll
        for (int n = 0; n < 2; n++) {
            #pragma unroll
            for (int r = 0; r < 4; r++) sc[m][n][r] = 0.f;
            #pragma unroll
            for (int k = 0; k < 4; k++)
                mma16(sc[m][n], qf[m][k], bk[n][k]);
        }

    #pragma unroll
    for (int m = 0; m < 2; m++) {
        float v[2][4];
        #pragma unroll
        for (int n = 0; n < 2; n++)
            #pragma unroll
            for (int r = 0; r < 4; r++) v[n][r] = sc[m][n][r] * SCALE;

        float mx0 = fmaxf(fmaxf(v[0][0], v[0][1]), fmaxf(v[1][0], v[1][1]));
        float mx1 = fmaxf(fmaxf(v[0][2], v[0][3]), fmaxf(v[1][2], v[1][3]));
        mx0 = fmaxf(mx0, __shfl_xor_sync(0xffffffffu, mx0, 1));
        mx0 = fmaxf(mx0, __shfl_xor_sync(0xffffffffu, mx0, 2));
        mx1 = fmaxf(mx1, __shfl_xor_sync(0xffffffffu, mx1, 1));
        mx1 = fmaxf(mx1, __shfl_xor_sync(0xffffffffu, mx1, 2));

        float e[2][4];
        #pragma unroll
        for (int n = 0; n < 2; n++) {
            e[n][0] = expf(v[n][0] - mx0);
            e[n][1] = expf(v[n][1] - mx0);
            e[n][2] = expf(v[n][2] - mx1);
            e[n][3] = expf(v[n][3] - mx1);
        }
        float s0 = e[0][0] + e[0][1] + e[1][0] + e[1][1];
        float s1 = e[0][2] + e[0][3] + e[1][2] + e[1][3];
        s0 += __shfl_xor_sync(0xffffffffu, s0, 1);
        s0 += __shfl_xor_sync(0xffffffffu, s0, 2);
        s1 += __shfl_xor_sync(0xffffffffu, s1, 1);
        s1 += __shfl_xor_sync(0xffffffffu, s1, 2);
        float i0 = gate / s0, i1 = gate / s1;

        uint32_t pf[4];
        pf[0] = pack_bf2(e[0][0]*i0, e[0][1]*i0);
        pf[1] = pack_bf2(e[0][2]*i1, e[0][3]*i1);
        pf[2] = pack_bf2(e[1][0]*i0, e[1][1]*i0);
        pf[3] = pack_bf2(e[1][2]*i1, e[1][3]*i1);

        #pragma unroll
        for (int n8 = 0; n8 < 8; n8++)
            mma16(out[m][n8], pf, bv[n8]);
    }
}

__global__ __launch_bounds__(128)
void attn_mma() {
    __shared__ bf16 sQ[128*72];
    __shared__ bf16 sKa[16*72], sKd[16*72];
    __shared__ bf16 sVa[64*VP], sVd[64*VP];
    const int b = blockIdx.z, h = blockIdx.y, bx = blockIdx.x;
    const int t = threadIdx.x, lane = t & 31, w = t >> 5;

    const long qbase = ((long)(b*Ssz) + bx*128) * Dsz + h*HD;
    #pragma unroll
    for (int i = 0; i < 8; i++) {
        int idx = i*128 + t;
        int row = idx >> 3, c8 = idx & 7;
        uint4 v = *(const uint4*)(g_qb + qbase + (long)row*Dsz + c8*8);
        *(uint4*)&sQ[row*72 + c8*8] = v;
    }
    {
        const float* ka = g_ka + ((long)b*NTOK)*Dsz + h*HD;
        const float* kd = g_kd + ((long)b*NTOK)*Dsz + h*HD;
        #pragma unroll
        for (int i = 0; i < 4; i++) {
            int idx = i*128 + t;
            int d2 = idx & 31, tok = idx >> 5;
            float2 va = *(const float2*)(ka + (long)tok*Dsz + 2*d2);
            float2 vd = *(const float2*)(kd + (long)tok*Dsz + 2*d2);
            *(uint32_t*)&sKa[tok*72 + 2*d2] = pack_bf2(va.x, va.y);
            *(uint32_t*)&sKd[tok*72 + 2*d2] = pack_bf2(vd.x, vd.y);
        }
    }
    {
        const float* va = g_va + ((long)b*NTOK)*Dsz + h*HD;
        const float* vd = g_vd + ((long)b*NTOK)*Dsz + h*HD;
        #pragma unroll
        for (int i = 0; i < 8; i++) {
            int idx = i*128 + t;
            int d = idx & 63, tok = idx >> 6;
            sVa[d*VP + tok] = __float2bfloat16_rn(va[(long)tok*Dsz + d]);
            sVd[d*VP + tok] = __float2bfloat16_rn(vd[(long)tok*Dsz + d]);
        }
    }
    __syncthreads();

    const float ga = g_gate[b*2+0], gd = g_gate[b*2+1];

    uint32_t qf[2][4][4];
    #pragma unroll
    for (int m = 0; m < 2; m++)
        #pragma unroll
        for (int k = 0; k < 4; k++) {
            uint32_t addr = smem_u32(
                &sQ[(w*32 + m*16 + (lane & 15))*72 + k*16 + ((lane >> 4) << 3)]);
            ldsm4(qf[m][k], addr);
        }

    float out[2][8][4];
    #pragma unroll
    for (int m = 0; m < 2; m++)
        #pragma unroll
        for (int n = 0; n < 8; n++)
            #pragma unroll
            for (int r = 0; r < 4; r++) out[m][n][r] = 0.f;

    attend_branch(sKa, sVa, ga, lane, qf, out);
    attend_branch(sKd, sVd, gd, lane, qf, out);

    const long zbase = ((long)(b*Ssz) + bx*128 + w*32) * Dsz + h*HD;
    const int r = lane >> 2, c = 2 * (lane & 3);
    #pragma unroll
    for (int m = 0; m < 2; m++)
        #pragma unroll
        for (int n8 = 0; n8 < 8; n8++) {
            long ro = zbase + (long)(m*16 + r) * Dsz + n8*8 + c;
            *(uint32_t*)(g_z + ro)          = pack_bf2(out[m][n8][0], out[m][n8][1]);
            *(uint32_t*)(g_z + ro + 8*Dsz)  = pack_bf2(out[m][n8][2], out[m][n8][3]);
        }
}

// ---------------- launch ----------------------------------------------------
extern "C" void kernel_launch(void* const* d_in, const int* in_sizes, int n_in,
                              void* d_out, int out_size) {
    const float* hidden  = (const float*)d_in[0];
    const float* enc     = (const float*)d_in[1];
    const float* w_q     = (const float*)d_in[2];
    const float* w_k     = (const float*)d_in[3];
    const float* w_v     = (const float*)d_in[4];
    const float* w_k_dis = (const float*)d_in[5];
    const float* w_v_dis = (const float*)d_in[6];
    const float* w_gate  = (const float*)d_in[7];
    const float* b_gate  = (const float*)d_in[8];
    const float* a_logit = (const float*)d_in[9];
    const float* d_logit = (const float*)d_in[10];
    const float* w_out   = (const float*)d_in[11];
    const float* b_out   = (const float*)d_in[12];
    float* out = (float*)d_out;

    bf16 *anat_p, *dis_p, *z_p, *hidb_p, *qb_p, *wq_p, *wout_p, *wka_p, *wva_p, *wkd_p, *wvd_p;
    float *ka_p, *va_p, *kd_p, *vd_p;
    cudaGetSymbolAddress((void**)&anat_p, g_anat);
    cudaGetSymbolAddress((void**)&dis_p,  g_dis);
    cudaGetSymbolAddress((void**)&ka_p,   g_ka);
    cudaGetSymbolAddress((void**)&va_p,   g_va);
    cudaGetSymbolAddress((void**)&kd_p,   g_kd);
    cudaGetSymbolAddress((void**)&vd_p,   g_vd);
    cudaGetSymbolAddress((void**)&qb_p,   g_qb);
    cudaGetSymbolAddress((void**)&z_p,    g_z);
    cudaGetSymbolAddress((void**)&hidb_p, g_hidb);
    cudaGetSymbolAddress((void**)&wq_p,   g_wq);
    cudaGetSymbolAddress((void**)&wout_p, g_wout);
    cudaGetSymbolAddress((void**)&wka_p,  g_wka);
    cudaGetSymbolAddress((void**)&wva_p,  g_wva);
    cudaGetSymbolAddress((void**)&wkd_p,  g_wkd);
    cudaGetSymbolAddress((void**)&wvd_p,  g_wvd);

    cudaFuncSetAttribute(proj_all, cudaFuncAttributeMaxDynamicSharedMemorySize, GEMM_SMEM);
    cudaFuncSetAttribute(gemm_out, cudaFuncAttributeMaxDynamicSharedMemorySize, GEMM_SMEM);

    // fused prep: hidden f2bf + weight f2bf + gather + gate
    {
        PrepArgs pa;
        pa.hidden = hidden;  pa.enc = enc;
        pa.src[0] = w_q;     pa.dst[0] = wq_p;
        pa.src[1] = w_out;   pa.dst[1] = wout_p;
        pa.src[2] = w_k;     pa.dst[2] = wka_p;
        pa.src[3] = w_v;     pa.dst[3] = wva_p;
        pa.src[4] = w_k_dis; pa.dst[4] = wkd_p;
        pa.src[5] = w_v_dis; pa.dst[5] = wvd_p;
        pa.w_gate = w_gate;  pa.b_gate = b_gate;
        pa.a_logit = a_logit; pa.d_logit = d_logit;
        prep_all<<<PREP_BLKS, 256>>>(pa);
    }

    // merged Q + KV projections: grid (10, 128 Q + 8 KV)
    {
        ProjBatch pb;
        pb.A[0] = hidb_p; pb.W[0] = wq_p;  pb.C[0] = qb_p; pb.K[0] = Dsz;
        pb.A[1] = anat_p; pb.W[1] = wka_p; pb.C[1] = ka_p; pb.K[1] = CRS;
        pb.A[2] = anat_p; pb.W[2] = wva_p; pb.C[2] = va_p; pb.K[2] = CRS;
        pb.A[3] = dis_p;  pb.W[3] = wkd_p; pb.C[3] = kd_p; pb.K[3] = CRS;
        pb.A[4] = dis_p;  pb.W[4] = wvd_p; pb.C[4] = vd_p; pb.K[4] = CRS;
        dim3 grid(Dsz/128, 128 + 8);
        proj_all<<<grid, 512, GEMM_SMEM>>>(pb);
    }
    // mma attention + gating
    {
        dim3 grid(Ssz/128, HEADS, Bsz);
        attn_mma<<<grid, 128>>>();
    }
    // out projection + bias + residual
    {
        dim3 grid(Dsz/128, MS/256);
        gemm_out<<<grid, 512, GEMM_SMEM>>>(z_p, wout_p, out, Dsz, Dsz, b_out, hidden);
    }
}

// round 15
// speedup vs baseline: 1.0539x; 1.0539x over previous
#include <cuda_runtime.h>
#include <cuda_bf16.h>
#include <math.h>
#include <stdint.h>

#define Bsz   32
#define Ssz   1024
#define Dsz   1280
#define CRS   768
#define HEADS 20
#define HD    64
#define NTOK  16
#define ETOK  48
#define MS    (Bsz*Ssz)
#define SCALE 0.125f

typedef __nv_bfloat16 bf16;

// ---------------- scratch (device globals: allocation-free) ----------------
__device__ bf16  g_qb [MS*Dsz];
__device__ bf16  g_z  [MS*Dsz];
__device__ bf16  g_hidb[MS*Dsz];
__device__ bf16  g_anat[Bsz*NTOK*CRS];
__device__ bf16  g_dis [Bsz*NTOK*CRS];
__device__ float g_ka [Bsz*NTOK*Dsz];
__device__ float g_va [Bsz*NTOK*Dsz];
__device__ float g_kd [Bsz*NTOK*Dsz];
__device__ float g_vd [Bsz*NTOK*Dsz];
__device__ float g_gate[Bsz*2];
__device__ bf16  g_wq  [Dsz*Dsz];
__device__ bf16  g_wout[Dsz*Dsz];
__device__ bf16  g_wka [Dsz*CRS];
__device__ bf16  g_wva [Dsz*CRS];
__device__ bf16  g_wkd [Dsz*CRS];
__device__ bf16  g_wvd [Dsz*CRS];

// ---------------- helpers ---------------------------------------------------
__device__ __forceinline__ uint32_t smem_u32(const void* p) {
    uint32_t a;
    asm("{ .reg .u64 t; cvta.to.shared.u64 t, %1; cvt.u32.u64 %0, t; }" : "=r"(a) : "l"(p));
    return a;
}
__device__ __forceinline__ void cp16(uint32_t dst, const void* src) {
    asm volatile("cp.async.cg.shared.global [%0], [%1], 16;" :: "r"(dst), "l"(src));
}
#define CP_COMMIT() asm volatile("cp.async.commit_group;" ::: "memory")

__device__ __forceinline__ uint32_t pack_bf2(float lo, float hi) {
    __nv_bfloat162 v = __floats2bfloat162_rn(lo, hi);
    return *(uint32_t*)&v;
}
__device__ __forceinline__ void ldsm4(uint32_t* r, uint32_t addr) {
    asm volatile("ldmatrix.sync.aligned.m8n8.x4.shared.b16 {%0,%1,%2,%3}, [%4];"
                 : "=r"(r[0]), "=r"(r[1]), "=r"(r[2]), "=r"(r[3]) : "r"(addr));
}
__device__ __forceinline__ void mma16(float* d, const uint32_t* a, const uint32_t* b) {
    asm volatile(
        "mma.sync.aligned.m16n8k16.row.col.f32.bf16.bf16.f32 "
        "{%0,%1,%2,%3}, {%4,%5,%6,%7}, {%8,%9}, {%0,%1,%2,%3};"
        : "+f"(d[0]), "+f"(d[1]), "+f"(d[2]), "+f"(d[3])
        : "r"(a[0]), "r"(a[1]), "r"(a[2]), "r"(a[3]), "r"(b[0]), "r"(b[1]));
}

// ---------------- bf16 mma.sync GEMM: BM=BN=128, BK=64, 3-stage -------------
// 8 warps (2m x 4n), warp tile 64x32, 256 threads, 2 CTAs/SM.
#define LDE 72
#define TILE_E (128*LDE)
#define TILE_BYTES (TILE_E*2)            // 18432
#define STAGE_BYTES (2*TILE_BYTES)       // 36864
#define GEMM_SMEM (3*STAGE_BYTES)        // 110592 (2 CTAs = 221 KB <= 228 KB)

struct ProjBatch {
    const bf16* A[5];
    const bf16* W[5];
    void*       C[5];
    int         K[5];
};

__device__ __forceinline__ void gemm_core(
    const bf16* __restrict__ A, const bf16* __restrict__ W,
    void* __restrict__ C, int N, int K, int bm, int bn, bool obf,
    const float* __restrict__ bias, const float* __restrict__ res,
    uint32_t sbase, int t, int lane, int warp_m, int warp_n)
{
    const int NIT = K / 64;

    const uint32_t aLane = ((uint32_t)(warp_m*64 + (lane & 15)) * LDE
                          + ((lane >> 4) << 3)) * 2;
    const uint32_t bLane = ((uint32_t)(warp_n*32 + ((lane >> 4) << 3) + (lane & 7)) * LDE
                          + (((lane >> 3) & 1) << 3)) * 2;

    float acc[4][4][4];
    #pragma unroll
    for (int i = 0; i < 4; i++)
        #pragma unroll
        for (int j = 0; j < 4; j++)
            #pragma unroll
            for (int r = 0; r < 4; r++) acc[i][j][r] = 0.f;

    #define LOAD_STAGE(IT, S) do {                                             \
        const bf16* Ab = A + (long)bm * K + (IT) * 64;                         \
        const bf16* Wb = W + (long)bn * K + (IT) * 64;                         \
        uint32_t dA = sbase + (S) * STAGE_BYTES;                               \
        uint32_t dB = dA + TILE_BYTES;                                         \
        _Pragma("unroll")                                                      \
        for (int i = 0; i < 4; i++) {                                          \
            int idx = i * 256 + t; int row = idx >> 3, g = idx & 7;            \
            cp16(dA + row * (LDE*2) + g * 16, Ab + (long)row * K + g * 8);     \
        }                                                                      \
        _Pragma("unroll")                                                      \
        for (int i = 0; i < 4; i++) {                                          \
            int idx = i * 256 + t; int row = idx >> 3, g = idx & 7;            \
            cp16(dB + row * (LDE*2) + g * 16, Wb + (long)row * K + g * 8);     \
        }                                                                      \
        CP_COMMIT();                                                           \
    } while (0)

    LOAD_STAGE(0, 0);
    if (NIT > 1) LOAD_STAGE(1, 1);

    for (int it = 0; it < NIT; it++) {
        int s = it % 3;
        if (it + 1 < NIT) asm volatile("cp.async.wait_group 1;" ::: "memory");
        else              asm volatile("cp.async.wait_group 0;" ::: "memory");
        __syncthreads();
        if (it + 2 < NIT)
            LOAD_STAGE(it + 2, (it + 2) % 3);

        const uint32_t aBase = sbase + s * STAGE_BYTES + aLane;
        const uint32_t bBase = sbase + s * STAGE_BYTES + TILE_BYTES + bLane;
        #pragma unroll
        for (int ks = 0; ks < 4; ks++) {
            uint32_t a[4][4], bb[2][4];
            #pragma unroll
            for (int mt = 0; mt < 4; mt++)
                ldsm4(a[mt], aBase + mt * (16*LDE*2) + ks * 32);
            #pragma unroll
            for (int j = 0; j < 2; j++)
                ldsm4(bb[j], bBase + j * (16*LDE*2) + ks * 32);
            #pragma unroll
            for (int mt = 0; mt < 4; mt++)
                #pragma unroll
                for (int nt = 0; nt < 4; nt++)
                    mma16(acc[mt][nt], a[mt], &bb[nt >> 1][(nt & 1) * 2]);
        }
    }

    #pragma unroll
    for (int mt = 0; mt < 4; mt++) {
        #pragma unroll
        for (int nt = 0; nt < 4; nt++) {
            int row = bm + warp_m * 64 + mt * 16 + (lane >> 2);
            int col = bn + warp_n * 32 + nt * 8 + 2 * (lane & 3);
            float2 v0 = make_float2(acc[mt][nt][0], acc[mt][nt][1]);
            float2 v1 = make_float2(acc[mt][nt][2], acc[mt][nt][3]);
            if (obf) {
                bf16* Cb = (bf16*)C;
                *(uint32_t*)(Cb + (long)row * N + col)       = pack_bf2(v0.x, v0.y);
                *(uint32_t*)(Cb + (long)(row + 8) * N + col) = pack_bf2(v1.x, v1.y);
            } else {
                float* Cf = (float*)C;
                if (bias) {
                    float2 bb2 = *(const float2*)(bias + col);
                    v0.x += bb2.x; v0.y += bb2.y; v1.x += bb2.x; v1.y += bb2.y;
                }
                if (res) {
                    float2 r0 = *(const float2*)(res + (long)row * N + col);
                    float2 r1 = *(const float2*)(res + (long)(row + 8) * N + col);
                    v0.x += r0.x; v0.y += r0.y; v1.x += r1.x; v1.y += r1.y;
                }
                *(float2*)(Cf + (long)row * N + col) = v0;
                *(float2*)(Cf + (long)(row + 8) * N + col) = v1;
            }
        }
    }
    #undef LOAD_STAGE
}

// merged projection kernel: grid (N/128, 272). y<256 -> Q tiles; y>=256 -> KV.
__global__ __launch_bounds__(256, 2)
void proj_all(ProjBatch pb) {
    extern __shared__ bf16 sm[];
    const int t = threadIdx.x;
    const int lane = t & 31, wid = t >> 5;
    const int bn = blockIdx.x * 128;
    const uint32_t sbase = smem_u32(sm);

    int e, bm;
    if (blockIdx.y < 256) { e = 0; bm = blockIdx.y * 128; }
    else { int y = blockIdx.y - 256; e = 1 + (y >> 2); bm = (y & 3) * 128; }

    gemm_core(pb.A[e], pb.W[e], pb.C[e], Dsz, pb.K[e], bm, bn, (e == 0),
              nullptr, nullptr, sbase, t, lane, wid >> 2, wid & 3);
}

__global__ __launch_bounds__(256, 2)
void gemm_out(const bf16* __restrict__ A, const bf16* __restrict__ W,
              float* __restrict__ C, int N, int K,
              const float* __restrict__ bias, const float* __restrict__ res) {
    extern __shared__ bf16 sm[];
    const int t = threadIdx.x;
    const int lane = t & 31, wid = t >> 5;
    gemm_core(A, W, C, N, K, blockIdx.y * 128, blockIdx.x * 128, false,
              bias, res, smem_u32(sm), t, lane, wid >> 2, wid & 3);
}

// ---------------- fused prep: conversions + gather + gate (one launch) ------
// hidden handled with 4 float4s per thread (MLP=4).
#define HID_BLK  10240                   // 10240 * 256 * 4 float4 = MS*Dsz/4
#define WQ_BLK   1600
#define WK_BLK   960
#define W_BLK    (2*WQ_BLK + 4*WK_BLK)   // 7040
#define GATH_BLK 1536
#define PREP_BLKS (HID_BLK + W_BLK + GATH_BLK + 32)

struct PrepArgs {
    const float* hidden;
    const float* enc;
    const float* src[6];
    bf16*        dst[6];
    const float* w_gate;
    const float* b_gate;
    const float* a_logit;
    const float* d_logit;
};

__global__ __launch_bounds__(256)
void prep_all(PrepArgs pa) {
    int bid = blockIdx.x;
    int tid = threadIdx.x;

    if (bid < HID_BLK) {                   // hidden fp32 -> bf16, 4 float4/thread
        int base = bid * 1024 + tid;
        float4 v0 = ((const float4*)pa.hidden)[base];
        float4 v1 = ((const float4*)pa.hidden)[base + 256];
        float4 v2 = ((const float4*)pa.hidden)[base + 512];
        float4 v3 = ((const float4*)pa.hidden)[base + 768];
        uint2 o0, o1, o2, o3;
        o0.x = pack_bf2(v0.x, v0.y); o0.y = pack_bf2(v0.z, v0.w);
        o1.x = pack_bf2(v1.x, v1.y); o1.y = pack_bf2(v1.z, v1.w);
        o2.x = pack_bf2(v2.x, v2.y); o2.y = pack_bf2(v2.z, v2.w);
        o3.x = pack_bf2(v3.x, v3.y); o3.y = pack_bf2(v3.z, v3.w);
        ((uint2*)g_hidb)[base]       = o0;
        ((uint2*)g_hidb)[base + 256] = o1;
        ((uint2*)g_hidb)[base + 512] = o2;
        ((uint2*)g_hidb)[base + 768] = o3;
        return;
    }
    bid -= HID_BLK;
    if (bid < W_BLK) {
        int seg, base;
        if (bid < WQ_BLK)               { seg = 0; base = bid; }
        else if (bid < 2*WQ_BLK)        { seg = 1; base = bid - WQ_BLK; }
        else { int y = bid - 2*WQ_BLK;    seg = 2 + y / WK_BLK; base = y % WK_BLK; }
        int i = base * 256 + tid;
        float4 v = ((const float4*)pa.src[seg])[i];
        uint2 o;
        o.x = pack_bf2(v.x, v.y);
        o.y = pack_bf2(v.z, v.w);
        ((uint2*)pa.dst[seg])[i] = o;
        return;
    }
    bid -= W_BLK;
    if (bid < GATH_BLK) {
        int i = bid * 256 + tid;
        int c = i % CRS;
        int tt = (i / CRS) % NTOK;
        int b = i / (CRS*NTOK);
        g_dis [i] = __float2bfloat16_rn(pa.enc[((long)b*ETOK + tt)        * CRS + c]);
        g_anat[i] = __float2bfloat16_rn(pa.enc[((long)b*ETOK + NTOK + tt) * CRS + c]);
        return;
    }
    bid -= GATH_BLK;
    {
        int b = bid;
        __shared__ float red[256];
        float partial = 0.f;
        for (int c = tid; c < CRS; c += 256) {
            float s = 0.f;
            #pragma unroll
            for (int t2 = 0; t2 < NTOK; t2++)
                s += pa.enc[((long)b*ETOK + t2) * CRS + c];
            partial += (s * (1.0f/NTOK)) * pa.w_gate[c];
        }
        red[tid] = partial;
        __syncthreads();
        for (int off = 128; off > 0; off >>= 1) {
            if (tid < off) red[tid] += red[tid + off];
            __syncthreads();
        }
        if (tid == 0) {
            float shift = red[0] + pa.b_gate[0];
            g_gate[b*2+0] = 1.0f / (1.0f + expf(-(pa.a_logit[0] - shift)));
            g_gate[b*2+1] = 1.0f / (1.0f + expf(-(pa.d_logit[0] + shift)));
        }
    }
}

// ---------------- mma attention: one CTA = 128 queries x 1 head -------------
#define VP 24

__device__ __forceinline__ void attend_branch(
    const bf16* sK, const bf16* sV, float gate, int lane,
    const uint32_t (&qf)[2][4][4], float (&out)[2][8][4])
{
    uint32_t bk[2][4][2];
    #pragma unroll
    for (int n = 0; n < 2; n++)
        #pragma unroll
        for (int k = 0; k < 4; k++) {
            const bf16* p = &sK[(n*8 + (lane >> 2))*72 + k*16 + 2*(lane & 3)];
            bk[n][k][0] = *(const uint32_t*)p;
            bk[n][k][1] = *(const uint32_t*)(p + 8);
        }
    uint32_t bv[8][2];
    #pragma unroll
    for (int n8 = 0; n8 < 8; n8++) {
        const bf16* p = &sV[(n8*8 + (lane >> 2))*VP + 2*(lane & 3)];
        bv[n8][0] = *(const uint32_t*)p;
        bv[n8][1] = *(const uint32_t*)(p + 8);
    }

    float sc[2][2][4];
    #pragma unroll
    for (int m = 0; m < 2; m++)
        #pragma unroll
        for (int n = 0; n < 2; n++) {
            #pragma unroll
            for (int r = 0; r < 4; r++) sc[m][n][r] = 0.f;
            #pragma unroll
            for (int k = 0; k < 4; k++)
                mma16(sc[m][n], qf[m][k], bk[n][k]);
        }

    #pragma unroll
    for (int m = 0; m < 2; m++) {
        float v[2][4];
        #pragma unroll
        for (int n = 0; n < 2; n++)
            #pragma unroll
            for (int r = 0; r < 4; r++) v[n][r] = sc[m][n][r] * SCALE;

        float mx0 = fmaxf(fmaxf(v[0][0], v[0][1]), fmaxf(v[1][0], v[1][1]));
        float mx1 = fmaxf(fmaxf(v[0][2], v[0][3]), fmaxf(v[1][2], v[1][3]));
        mx0 = fmaxf(mx0, __shfl_xor_sync(0xffffffffu, mx0, 1));
        mx0 = fmaxf(mx0, __shfl_xor_sync(0xffffffffu, mx0, 2));
        mx1 = fmaxf(mx1, __shfl_xor_sync(0xffffffffu, mx1, 1));
        mx1 = fmaxf(mx1, __shfl_xor_sync(0xffffffffu, mx1, 2));

        float e[2][4];
        #pragma unroll
        for (int n = 0; n < 2; n++) {
            e[n][0] = expf(v[n][0] - mx0);
            e[n][1] = expf(v[n][1] - mx0);
            e[n][2] = expf(v[n][2] - mx1);
            e[n][3] = expf(v[n][3] - mx1);
        }
        float s0 = e[0][0] + e[0][1] + e[1][0] + e[1][1];
        float s1 = e[0][2] + e[0][3] + e[1][2] + e[1][3];
        s0 += __shfl_xor_sync(0xffffffffu, s0, 1);
        s0 += __shfl_xor_sync(0xffffffffu, s0, 2);
        s1 += __shfl_xor_sync(0xffffffffu, s1, 1);
        s1 += __shfl_xor_sync(0xffffffffu, s1, 2);
        float i0 = gate / s0, i1 = gate / s1;

        uint32_t pf[4];
        pf[0] = pack_bf2(e[0][0]*i0, e[0][1]*i0);
        pf[1] = pack_bf2(e[0][2]*i1, e[0][3]*i1);
        pf[2] = pack_bf2(e[1][0]*i0, e[1][1]*i0);
        pf[3] = pack_bf2(e[1][2]*i1, e[1][3]*i1);

        #pragma unroll
        for (int n8 = 0; n8 < 8; n8++)
            mma16(out[m][n8], pf, bv[n8]);
    }
}

__global__ __launch_bounds__(128)
void attn_mma() {
    __shared__ bf16 sQ[128*72];
    __shared__ bf16 sKa[16*72], sKd[16*72];
    __shared__ bf16 sVa[64*VP], sVd[64*VP];
    const int b = blockIdx.z, h = blockIdx.y, bx = blockIdx.x;
    const int t = threadIdx.x, lane = t & 31, w = t >> 5;

    const long qbase = ((long)(b*Ssz) + bx*128) * Dsz + h*HD;
    #pragma unroll
    for (int i = 0; i < 8; i++) {
        int idx = i*128 + t;
        int row = idx >> 3, c8 = idx & 7;
        uint4 v = *(const uint4*)(g_qb + qbase + (long)row*Dsz + c8*8);
        *(uint4*)&sQ[row*72 + c8*8] = v;
    }
    {
        const float* ka = g_ka + ((long)b*NTOK)*Dsz + h*HD;
        const float* kd = g_kd + ((long)b*NTOK)*Dsz + h*HD;
        #pragma unroll
        for (int i = 0; i < 4; i++) {
            int idx = i*128 + t;
            int d2 = idx & 31, tok = idx >> 5;
            float2 va = *(const float2*)(ka + (long)tok*Dsz + 2*d2);
            float2 vd = *(const float2*)(kd + (long)tok*Dsz + 2*d2);
            *(uint32_t*)&sKa[tok*72 + 2*d2] = pack_bf2(va.x, va.y);
            *(uint32_t*)&sKd[tok*72 + 2*d2] = pack_bf2(vd.x, vd.y);
        }
    }
    {
        const float* va = g_va + ((long)b*NTOK)*Dsz + h*HD;
        const float* vd = g_vd + ((long)b*NTOK)*Dsz + h*HD;
        #pragma unroll
        for (int i = 0; i < 8; i++) {
            int idx = i*128 + t;
            int d = idx & 63, tok = idx >> 6;
            sVa[d*VP + tok] = __float2bfloat16_rn(va[(long)tok*Dsz + d]);
            sVd[d*VP + tok] = __float2bfloat16_rn(vd[(long)tok*Dsz + d]);
        }
    }
    __syncthreads();

    const float ga = g_gate[b*2+0], gd = g_gate[b*2+1];

    uint32_t qf[2][4][4];
    #pragma unroll
    for (int m = 0; m < 2; m++)
        #pragma unroll
        for (int k = 0; k < 4; k++) {
            uint32_t addr = smem_u32(
                &sQ[(w*32 + m*16 + (lane & 15))*72 + k*16 + ((lane >> 4) << 3)]);
            ldsm4(qf[m][k], addr);
        }

    float out[2][8][4];
    #pragma unroll
    for (int m = 0; m < 2; m++)
        #pragma unroll
        for (int n = 0; n < 8; n++)
            #pragma unroll
            for (int r = 0; r < 4; r++) out[m][n][r] = 0.f;

    attend_branch(sKa, sVa, ga, lane, qf, out);
    attend_branch(sKd, sVd, gd, lane, qf, out);

    const long zbase = ((long)(b*Ssz) + bx*128 + w*32) * Dsz + h*HD;
    const int r = lane >> 2, c = 2 * (lane & 3);
    #pragma unroll
    for (int m = 0; m < 2; m++)
        #pragma unroll
        for (int n8 = 0; n8 < 8; n8++) {
            long ro = zbase + (long)(m*16 + r) * Dsz + n8*8 + c;
            *(uint32_t*)(g_z + ro)          = pack_bf2(out[m][n8][0], out[m][n8][1]);
            *(uint32_t*)(g_z + ro + 8*Dsz)  = pack_bf2(out[m][n8][2], out[m][n8][3]);
        }
}

// ---------------- launch ----------------------------------------------------
extern "C" void kernel_launch(void* const* d_in, const int* in_sizes, int n_in,
                              void* d_out, int out_size) {
    const float* hidden  = (const float*)d_in[0];
    const float* enc     = (const float*)d_in[1];
    const float* w_q     = (const float*)d_in[2];
    const float* w_k     = (const float*)d_in[3];
    const float* w_v     = (const float*)d_in[4];
    const float* w_k_dis = (const float*)d_in[5];
    const float* w_v_dis = (const float*)d_in[6];
    const float* w_gate  = (const float*)d_in[7];
    const float* b_gate  = (const float*)d_in[8];
    const float* a_logit = (const float*)d_in[9];
    const float* d_logit = (const float*)d_in[10];
    const float* w_out   = (const float*)d_in[11];
    const float* b_out   = (const float*)d_in[12];
    float* out = (float*)d_out;

    bf16 *anat_p, *dis_p, *z_p, *hidb_p, *qb_p, *wq_p, *wout_p, *wka_p, *wva_p, *wkd_p, *wvd_p;
    float *ka_p, *va_p, *kd_p, *vd_p;
    cudaGetSymbolAddress((void**)&anat_p, g_anat);
    cudaGetSymbolAddress((void**)&dis_p,  g_dis);
    cudaGetSymbolAddress((void**)&ka_p,   g_ka);
    cudaGetSymbolAddress((void**)&va_p,   g_va);
    cudaGetSymbolAddress((void**)&kd_p,   g_kd);
    cudaGetSymbolAddress((void**)&vd_p,   g_vd);
    cudaGetSymbolAddress((void**)&qb_p,   g_qb);
    cudaGetSymbolAddress((void**)&z_p,    g_z);
    cudaGetSymbolAddress((void**)&hidb_p, g_hidb);
    cudaGetSymbolAddress((void**)&wq_p,   g_wq);
    cudaGetSymbolAddress((void**)&wout_p, g_wout);
    cudaGetSymbolAddress((void**)&wka_p,  g_wka);
    cudaGetSymbolAddress((void**)&wva_p,  g_wva);
    cudaGetSymbolAddress((void**)&wkd_p,  g_wkd);
    cudaGetSymbolAddress((void**)&wvd_p,  g_wvd);

    cudaFuncSetAttribute(proj_all, cudaFuncAttributeMaxDynamicSharedMemorySize, GEMM_SMEM);
    cudaFuncSetAttribute(gemm_out, cudaFuncAttributeMaxDynamicSharedMemorySize, GEMM_SMEM);

    // fused prep: hidden f2bf + weight f2bf + gather + gate
    {
        PrepArgs pa;
        pa.hidden = hidden;  pa.enc = enc;
        pa.src[0] = w_q;     pa.dst[0] = wq_p;
        pa.src[1] = w_out;   pa.dst[1] = wout_p;
        pa.src[2] = w_k;     pa.dst[2] = wka_p;
        pa.src[3] = w_v;     pa.dst[3] = wva_p;
        pa.src[4] = w_k_dis; pa.dst[4] = wkd_p;
        pa.src[5] = w_v_dis; pa.dst[5] = wvd_p;
        pa.w_gate = w_gate;  pa.b_gate = b_gate;
        pa.a_logit = a_logit; pa.d_logit = d_logit;
        prep_all<<<PREP_BLKS, 256>>>(pa);
    }

    // merged Q + KV projections (one launch, 2720 CTAs)
    {
        ProjBatch pb;
        pb.A[0] = hidb_p; pb.W[0] = wq_p;  pb.C[0] = qb_p; pb.K[0] = Dsz;
        pb.A[1] = anat_p; pb.W[1] = wka_p; pb.C[1] = ka_p; pb.K[1] = CRS;
        pb.A[2] = anat_p; pb.W[2] = wva_p; pb.C[2] = va_p; pb.K[2] = CRS;
        pb.A[3] = dis_p;  pb.W[3] = wkd_p; pb.C[3] = kd_p; pb.K[3] = CRS;
        pb.A[4] = dis_p;  pb.W[4] = wvd_p; pb.C[4] = vd_p; pb.K[4] = CRS;
        dim3 grid(Dsz/128, 256 + 16);
        proj_all<<<grid, 256, GEMM_SMEM>>>(pb);
    }
    // mma attention + gating
    {
        dim3 grid(Ssz/128, HEADS, Bsz);
        attn_mma<<<grid, 128>>>();
    }
    // out projection + bias + residual
    {
        dim3 grid(Dsz/128, MS/128);
        gemm_out<<<grid, 256, GEMM_SMEM>>>(z_p, wout_p, out, Dsz, Dsz, b_out, hidden);
    }
}